// round 11
// baseline (speedup 1.0000x reference)
#include <cuda_runtime.h>
#include <cuda_bf16.h>

// MaskCNN1: out[b,c,h,w] = (w < floor(W * percents[b])) ? x[b,c,h,w] : 0
// x [16, 64, 80, 1024] fp32, percents [16] fp32.
// R10: phase separation. Kernel A writes the fully-masked region (pure DRAM
// write stream, no read interleave -> better bus efficiency). Kernel B copies
// the valid region + straddle column (balanced R/W). Both span the full index
// space and early-exit off-phase threads (3 ALU ops). R7's cache hints kept:
// loads evict_last, stores evict_first.

using u64 = unsigned long long;

static constexpr int B = 16;
static constexpr int C = 64;
static constexpr int H = 80;
static constexpr int W = 1024;
static constexpr int W4 = W / 4;               // 256 float4 per row
static constexpr int PER_B4 = C * H * W4;      // 1,310,720 float4 per batch
static constexpr int UNROLL = 4;
static constexpr int BLOCK = 256;
static constexpr int PER_BLOCK = BLOCK * UNROLL;   // 1024 float4 (4 rows)

__device__ __forceinline__ float4 ld_hint(const float4* p, u64 pol) {
    float4 v;
    asm volatile("ld.global.nc.L2::cache_hint.v4.f32 {%0,%1,%2,%3}, [%4], %5;"
                 : "=f"(v.x), "=f"(v.y), "=f"(v.z), "=f"(v.w)
                 : "l"(p), "l"(pol));
    return v;
}
__device__ __forceinline__ void st_hint(float4* p, float4 v, u64 pol) {
    asm volatile("st.global.L2::cache_hint.v4.f32 [%0], {%1,%2,%3,%4}, %5;"
                 :: "l"(p), "f"(v.x), "f"(v.y), "f"(v.z), "f"(v.w), "l"(pol)
                 : "memory");
}

// ---------------- Kernel A: pure zero-fill of the fully-masked region ------
__global__ __launch_bounds__(BLOCK)
void mask_zero_kernel(const float* __restrict__ percents,
                      float4* __restrict__ out) {
    const int b   = blockIdx.y;
    const int tid = threadIdx.x;

    const float p = __ldg(&percents[b]);
    const int len = (int)((float)W * p);     // floor via truncation (p >= 0)

    const int pos = tid << 2;                // unroll-invariant column
    if (pos < len) return;                   // fully-masked float4s only

    u64 pol_first;
    asm volatile("createpolicy.fractional.L2::evict_first.b64 %0, 1.0;" : "=l"(pol_first));

    const long base = (long)b * PER_B4 + (long)blockIdx.x * PER_BLOCK + tid;
    const float4 z = make_float4(0.f, 0.f, 0.f, 0.f);
    #pragma unroll
    for (int i = 0; i < UNROLL; i++) st_hint(&out[base + i * W4], z, pol_first);
}

// ---------------- Kernel B: copy valid region + straddle column ------------
__global__ __launch_bounds__(BLOCK)
void mask_copy_kernel(const float4* __restrict__ x,
                      const float* __restrict__ percents,
                      float4* __restrict__ out) {
    const int b   = blockIdx.y;
    const int tid = threadIdx.x;

    const float p = __ldg(&percents[b]);
    const int len = (int)((float)W * p);

    const int pos = tid << 2;
    if (pos >= len) return;                  // handled by the zero pass

    u64 pol_last, pol_first;
    asm volatile("createpolicy.fractional.L2::evict_last.b64 %0, 1.0;"  : "=l"(pol_last));
    asm volatile("createpolicy.fractional.L2::evict_first.b64 %0, 1.0;" : "=l"(pol_first));

    const long base = (long)b * PER_B4 + (long)blockIdx.x * PER_BLOCK + tid;

    if (pos + 3 < len) {
        // fully valid: straight copy
        float4 v[UNROLL];
        #pragma unroll
        for (int i = 0; i < UNROLL; i++) v[i] = ld_hint(&x[base + i * W4], pol_last);
        #pragma unroll
        for (int i = 0; i < UNROLL; i++) st_hint(&out[base + i * W4], v[i], pol_first);
    } else {
        // straddling float4 (one column of 256): per-lane select
        const bool k0 = pos + 0 < len, k1 = pos + 1 < len,
                   k2 = pos + 2 < len, k3 = pos + 3 < len;
        float4 v[UNROLL];
        #pragma unroll
        for (int i = 0; i < UNROLL; i++) v[i] = ld_hint(&x[base + i * W4], pol_last);
        #pragma unroll
        for (int i = 0; i < UNROLL; i++) {
            v[i].x = k0 ? v[i].x : 0.f;
            v[i].y = k1 ? v[i].y : 0.f;
            v[i].z = k2 ? v[i].z : 0.f;
            v[i].w = k3 ? v[i].w : 0.f;
        }
        #pragma unroll
        for (int i = 0; i < UNROLL; i++) st_hint(&out[base + i * W4], v[i], pol_first);
    }
}

extern "C" void kernel_launch(void* const* d_in, const int* in_sizes, int n_in,
                              void* d_out, int out_size) {
    const float4* x        = (const float4*)d_in[0];
    const float*  percents = (const float*)d_in[1];
    float4*       out      = (float4*)d_out;

    dim3 grid(PER_B4 / PER_BLOCK, B, 1);   // 1280 x 16 blocks each
    mask_zero_kernel<<<grid, BLOCK>>>(percents, out);
    mask_copy_kernel<<<grid, BLOCK>>>(x, percents, out);
}

// round 13
// speedup vs baseline: 1.0794x; 1.0794x over previous
#include <cuda_runtime.h>
#include <cuda_bf16.h>

// MaskCNN1: out[b,c,h,w] = (w < floor(W * percents[b])) ? x[b,c,h,w] : 0
// x [16, 64, 80, 1024] fp32, percents [16] fp32.
// FINAL (R7 config, re-bench): float4, x4 unroll with stride W4=256 so the
// W-column (and mask predicate) is unroll-invariant -> one branch per thread,
// 4 front-batched LDG.128 + 4 STG.128. Fully-masked region never reads x.
// Loads: ld.global.nc + L2::evict_last policy (read set persists in L2 across
// graph replays). Stores: L2::evict_first (write stream is eviction victim).
// Roofline analysis (R1-R10): traffic is minimal (335MB writes + ~69MB reads);
// HBM write-dominated streams cap at ~5.8-5.9 TB/s on this part regardless of
// MLP/occupancy/phase structure -> ~69us kernel is the floor.

using u64 = unsigned long long;

static constexpr int B = 16;
static constexpr int C = 64;
static constexpr int H = 80;
static constexpr int W = 1024;
static constexpr int W4 = W / 4;               // 256 float4 per row
static constexpr int PER_B4 = C * H * W4;      // 1,310,720 float4 per batch
static constexpr int UNROLL = 4;
static constexpr int BLOCK = 256;
static constexpr int PER_BLOCK = BLOCK * UNROLL;   // 1024 float4 (4 rows)

__device__ __forceinline__ float4 ld_hint(const float4* p, u64 pol) {
    float4 v;
    asm volatile("ld.global.nc.L2::cache_hint.v4.f32 {%0,%1,%2,%3}, [%4], %5;"
                 : "=f"(v.x), "=f"(v.y), "=f"(v.z), "=f"(v.w)
                 : "l"(p), "l"(pol));
    return v;
}
__device__ __forceinline__ void st_hint(float4* p, float4 v, u64 pol) {
    asm volatile("st.global.L2::cache_hint.v4.f32 [%0], {%1,%2,%3,%4}, %5;"
                 :: "l"(p), "f"(v.x), "f"(v.y), "f"(v.z), "f"(v.w), "l"(pol)
                 : "memory");
}

__global__ __launch_bounds__(BLOCK)
void mask_cnn_kernel(const float4* __restrict__ x,
                     const float* __restrict__ percents,
                     float4* __restrict__ out) {
    const int b   = blockIdx.y;
    const int tid = threadIdx.x;

    // L2 policies: created once per thread (cheap fixed-lat ops).
    u64 pol_last, pol_first;
    asm volatile("createpolicy.fractional.L2::evict_last.b64 %0, 1.0;"  : "=l"(pol_last));
    asm volatile("createpolicy.fractional.L2::evict_first.b64 %0, 1.0;" : "=l"(pol_first));

    const float p = __ldg(&percents[b]);
    const int len = (int)((float)W * p);     // floor via int truncation (p >= 0)

    // Column == tid across the unroll (stride W4=256; block base % 256 == 0),
    // so the mask predicate is unroll-invariant.
    const int pos = tid << 2;

    const long base = (long)b * PER_B4 + (long)blockIdx.x * PER_BLOCK + tid;

    if (pos + 3 < len) {
        // fully valid: 4 front-batched loads (evict_last), 4 stores (evict_first)
        float4 v[UNROLL];
        #pragma unroll
        for (int i = 0; i < UNROLL; i++) v[i] = ld_hint(&x[base + i * W4], pol_last);
        #pragma unroll
        for (int i = 0; i < UNROLL; i++) st_hint(&out[base + i * W4], v[i], pol_first);
    } else if (pos >= len) {
        // fully masked: write zeros, never read x
        const float4 z = make_float4(0.f, 0.f, 0.f, 0.f);
        #pragma unroll
        for (int i = 0; i < UNROLL; i++) st_hint(&out[base + i * W4], z, pol_first);
    } else {
        // straddling float4 (one column of 256): per-lane select
        const bool k0 = pos + 0 < len, k1 = pos + 1 < len,
                   k2 = pos + 2 < len, k3 = pos + 3 < len;
        float4 v[UNROLL];
        #pragma unroll
        for (int i = 0; i < UNROLL; i++) v[i] = ld_hint(&x[base + i * W4], pol_last);
        #pragma unroll
        for (int i = 0; i < UNROLL; i++) {
            v[i].x = k0 ? v[i].x : 0.f;
            v[i].y = k1 ? v[i].y : 0.f;
            v[i].z = k2 ? v[i].z : 0.f;
            v[i].w = k3 ? v[i].w : 0.f;
        }
        #pragma unroll
        for (int i = 0; i < UNROLL; i++) st_hint(&out[base + i * W4], v[i], pol_first);
    }
}

extern "C" void kernel_launch(void* const* d_in, const int* in_sizes, int n_in,
                              void* d_out, int out_size) {
    const float4* x        = (const float4*)d_in[0];
    const float*  percents = (const float*)d_in[1];
    float4*       out      = (float4*)d_out;

    dim3 grid(PER_B4 / PER_BLOCK, B, 1);   // 1280 x 16 blocks
    mask_cnn_kernel<<<grid, BLOCK>>>(x, percents, out);
}

// round 14
// speedup vs baseline: 1.0798x; 1.0004x over previous
#include <cuda_runtime.h>
#include <cuda_bf16.h>

// MaskCNN1: out[b,c,h,w] = (w < floor(W * percents[b])) ? x[b,c,h,w] : 0
// x [16, 64, 80, 1024] fp32, percents [16] fp32.
// R13: single-variable experiment on the confirmed-best config: stores go
// write-through (__stwt / st.global.wt). If wt avoids L2 line allocation,
// the 335MB write stream stops displacing the evict_last read set (~69MB,
// fits the 126MB L2), which then fully persists across graph replays ->
// steady-state DRAM reads ~0. Loads unchanged from R7 (ld.global.nc +
// evict_last policy). Everything else identical to the 73.8us kernel.

using u64 = unsigned long long;

static constexpr int B = 16;
static constexpr int C = 64;
static constexpr int H = 80;
static constexpr int W = 1024;
static constexpr int W4 = W / 4;               // 256 float4 per row
static constexpr int PER_B4 = C * H * W4;      // 1,310,720 float4 per batch
static constexpr int UNROLL = 4;
static constexpr int BLOCK = 256;
static constexpr int PER_BLOCK = BLOCK * UNROLL;   // 1024 float4 (4 rows)

__device__ __forceinline__ float4 ld_hint(const float4* p, u64 pol) {
    float4 v;
    asm volatile("ld.global.nc.L2::cache_hint.v4.f32 {%0,%1,%2,%3}, [%4], %5;"
                 : "=f"(v.x), "=f"(v.y), "=f"(v.z), "=f"(v.w)
                 : "l"(p), "l"(pol));
    return v;
}
__device__ __forceinline__ void st_wt(float4* p, float4 v) {
    asm volatile("st.global.wt.v4.f32 [%0], {%1,%2,%3,%4};"
                 :: "l"(p), "f"(v.x), "f"(v.y), "f"(v.z), "f"(v.w) : "memory");
}

__global__ __launch_bounds__(BLOCK)
void mask_cnn_kernel(const float4* __restrict__ x,
                     const float* __restrict__ percents,
                     float4* __restrict__ out) {
    const int b   = blockIdx.y;
    const int tid = threadIdx.x;

    u64 pol_last;
    asm volatile("createpolicy.fractional.L2::evict_last.b64 %0, 1.0;" : "=l"(pol_last));

    const float p = __ldg(&percents[b]);
    const int len = (int)((float)W * p);     // floor via int truncation (p >= 0)

    // Column == tid across the unroll (stride W4=256; block base % 256 == 0),
    // so the mask predicate is unroll-invariant.
    const int pos = tid << 2;

    const long base = (long)b * PER_B4 + (long)blockIdx.x * PER_BLOCK + tid;

    if (pos + 3 < len) {
        // fully valid: 4 front-batched loads (evict_last), 4 wt stores
        float4 v[UNROLL];
        #pragma unroll
        for (int i = 0; i < UNROLL; i++) v[i] = ld_hint(&x[base + i * W4], pol_last);
        #pragma unroll
        for (int i = 0; i < UNROLL; i++) st_wt(&out[base + i * W4], v[i]);
    } else if (pos >= len) {
        // fully masked: write zeros, never read x
        const float4 z = make_float4(0.f, 0.f, 0.f, 0.f);
        #pragma unroll
        for (int i = 0; i < UNROLL; i++) st_wt(&out[base + i * W4], z);
    } else {
        // straddling float4 (one column of 256): per-lane select
        const bool k0 = pos + 0 < len, k1 = pos + 1 < len,
                   k2 = pos + 2 < len, k3 = pos + 3 < len;
        float4 v[UNROLL];
        #pragma unroll
        for (int i = 0; i < UNROLL; i++) v[i] = ld_hint(&x[base + i * W4], pol_last);
        #pragma unroll
        for (int i = 0; i < UNROLL; i++) {
            v[i].x = k0 ? v[i].x : 0.f;
            v[i].y = k1 ? v[i].y : 0.f;
            v[i].z = k2 ? v[i].z : 0.f;
            v[i].w = k3 ? v[i].w : 0.f;
        }
        #pragma unroll
        for (int i = 0; i < UNROLL; i++) st_wt(&out[base + i * W4], v[i]);
    }
}

extern "C" void kernel_launch(void* const* d_in, const int* in_sizes, int n_in,
                              void* d_out, int out_size) {
    const float4* x        = (const float4*)d_in[0];
    const float*  percents = (const float*)d_in[1];
    float4*       out      = (float4*)d_out;

    dim3 grid(PER_B4 / PER_BLOCK, B, 1);   // 1280 x 16 blocks
    mask_cnn_kernel<<<grid, BLOCK>>>(x, percents, out);
}